// round 13
// baseline (speedup 1.0000x reference)
#include <cuda_runtime.h>
#include <cuda_bf16.h>
#include <cstdint>
#include <math.h>

#define S_ 2048
#define DPROJ 4384

// ---------- scratch (floats) ----------
#define OFF_H        0ull
#define OFF_ZX       (OFF_H      + 4194304ull)   // 4096*1024
#define OFF_ACUM     (OFF_ZX     + 17956864ull)  // 4096*4384
#define OFF_XDT      (OFF_ACUM   + 131072ull)    // 64*2048
#define OFF_STATES   (OFF_XDT    + 8388608ull)   // 4096*2048
#define OFF_Y        (OFF_STATES + 16777216ull)  // 2*32*32*64*128
#define OFF_X1       (OFF_Y      + 8388608ull)
#define OFF_Q        (OFF_X1     + 4194304ull)
#define OFF_K        (OFF_Q      + 4194304ull)
#define OFF_V        (OFF_K      + 1048576ull)
#define OFF_AO       (OFF_V      + 1048576ull)
#define OFF_X2       (OFF_AO     + 4194304ull)
#define OFF_MLP      (OFF_X2     + 4194304ull)
#define OFF_WC       (OFF_MLP    + 12582912ull)  // tf32-rounded weights
#define SCRATCH_FLOATS (OFF_WC + 15499264ull)

__device__ float g_scratch[SCRATCH_FLOATS];

// ---------- helpers ----------
__device__ __forceinline__ float bsum256(float v, float* red) {
    #pragma unroll
    for (int o = 16; o; o >>= 1) v += __shfl_xor_sync(0xffffffffu, v, o);
    if ((threadIdx.x & 31) == 0) red[threadIdx.x >> 5] = v;
    __syncthreads();
    float t = red[0]+red[1]+red[2]+red[3]+red[4]+red[5]+red[6]+red[7];
    __syncthreads();
    return t;
}

__device__ __forceinline__ unsigned f2tf32(float f) {
    unsigned r; asm("cvt.rna.tf32.f32 %0, %1;" : "=r"(r) : "f"(f)); return r;
}
__device__ __forceinline__ float tf32r(float f) {   // round-to-tf32, stored as float
    return __uint_as_float(f2tf32(f));
}

__device__ __forceinline__ void cp16(float* s, const float* g, bool p) {
    unsigned sa = (unsigned)__cvta_generic_to_shared(s);
    int sz = p ? 16 : 0;
    asm volatile("cp.async.cg.shared.global [%0], [%1], 16, %2;" :: "r"(sa), "l"(g), "r"(sz));
}
#define CP_COMMIT() asm volatile("cp.async.commit_group;")
#define CP_WAIT(N)  asm volatile("cp.async.wait_group %0;" :: "n"(N))

__device__ __forceinline__ void mma8(float* c, const unsigned* a, const unsigned* b) {
    asm volatile("mma.sync.aligned.m16n8k8.row.col.f32.tf32.tf32.f32 "
        "{%0,%1,%2,%3},{%4,%5,%6,%7},{%8,%9},{%0,%1,%2,%3};"
        : "+f"(c[0]), "+f"(c[1]), "+f"(c[2]), "+f"(c[3])
        : "r"(a[0]), "r"(a[1]), "r"(a[2]), "r"(a[3]), "r"(b[0]), "r"(b[1]));
}

// ---------- tf32 pre-rounding of weights ----------
__global__ void __launch_bounds__(256) cvtw_kernel(const float4* __restrict__ in,
                                                   float4* __restrict__ out, int n4) {
    int i = blockIdx.x * 256 + threadIdx.x;
    if (i < n4) {
        float4 v = in[i];
        v.x = tf32r(v.x); v.y = tf32r(v.y); v.z = tf32r(v.z); v.w = tf32r(v.w);
        out[i] = v;
    }
}

// ---------- rmsnorm over 1024 (output tf32-rounded: GEMM operand) ----------
__global__ void __launch_bounds__(256) rmsnorm_kernel(const float* __restrict__ x,
                                                      const float* __restrict__ w,
                                                      float* __restrict__ out) {
    __shared__ float red[8];
    size_t row = blockIdx.x;
    const float* xr = x + (row << 10);
    float v[4]; float ss = 0.f;
    #pragma unroll
    for (int i = 0; i < 4; i++) { v[i] = xr[threadIdx.x + (i << 8)]; ss += v[i]*v[i]; }
    float tot = bsum256(ss, red);
    float sc = rsqrtf(tot * (1.f/1024.f) + 1e-5f);
    float* orow = out + (row << 10);
    #pragma unroll
    for (int i = 0; i < 4; i++) {
        int j = threadIdx.x + (i << 8);
        orow[j] = tf32r(v[i] * sc * w[j]);
    }
}

// ---------- layernorm over 1024 (output tf32-rounded: GEMM operand) ----------
__global__ void __launch_bounds__(256) layernorm_kernel(const float* __restrict__ x,
                                                        const float* __restrict__ w,
                                                        const float* __restrict__ bb,
                                                        float* __restrict__ out) {
    __shared__ float red[8];
    size_t row = blockIdx.x;
    const float* xr = x + (row << 10);
    float v[4]; float s = 0.f;
    #pragma unroll
    for (int i = 0; i < 4; i++) { v[i] = xr[threadIdx.x + (i << 8)]; s += v[i]; }
    float mean = bsum256(s, red) * (1.f/1024.f);
    float sv = 0.f;
    #pragma unroll
    for (int i = 0; i < 4; i++) { float d = v[i]-mean; sv += d*d; }
    float var = bsum256(sv, red) * (1.f/1024.f);
    float sc = rsqrtf(var + 1e-5f);
    float* orow = out + (row << 10);
    #pragma unroll
    for (int i = 0; i < 4; i++) {
        int j = threadIdx.x + (i << 8);
        orow[j] = tf32r((v[i]-mean)*sc*w[j] + bb[j]);
    }
}

// ---------- tensor-core TF32 GEMM (operands pre-rounded; no cvt in loop) ----------
// out[m,n] = A[m,:].W[n,:]  EPI: 0 none, 1 +res, 2 silu (output tf32-rounded)
template<int EPI>
__global__ void __launch_bounds__(256) gemm_tc(const float* __restrict__ A,
                                               const float* __restrict__ W,
                                               const float* __restrict__ res,
                                               float* __restrict__ out,
                                               int M, int N, int K) {
    __shared__ float As[2][128][20];
    __shared__ float Ws[2][128][20];
    int tid = threadIdx.x;
    int bm = blockIdx.y << 7, bn = blockIdx.x << 7;
    int lane = tid & 31, wid = tid >> 5;
    int wm = (wid & 1) << 6;
    int wn = (wid >> 1) << 5;

    int lr = tid >> 1;
    int lk = (tid & 1) << 3;
    const float* Ag = A + (size_t)(bm + lr) * K + lk;
    int wrow = bn + lr;
    bool wok = wrow < N;
    const float* Wg = W + (size_t)(wok ? wrow : (N-1)) * K + lk;

    float acc[4][4][4];
    #pragma unroll
    for (int i = 0; i < 4; i++)
        #pragma unroll
        for (int j = 0; j < 4; j++)
            #pragma unroll
            for (int q = 0; q < 4; q++) acc[i][j][q] = 0.f;

    int nk = K >> 4;
    cp16(&As[0][lr][lk],   Ag,     true);
    cp16(&As[0][lr][lk+4], Ag + 4, true);
    cp16(&Ws[0][lr][lk],   Wg,     wok);
    cp16(&Ws[0][lr][lk+4], Wg + 4, wok);
    CP_COMMIT();

    for (int t = 0; t < nk; t++) {
        if (t + 1 < nk) {
            int st = (t + 1) & 1;
            int ko = (t + 1) << 4;
            cp16(&As[st][lr][lk],   Ag + ko,     true);
            cp16(&As[st][lr][lk+4], Ag + ko + 4, true);
            cp16(&Ws[st][lr][lk],   Wg + ko,     wok);
            cp16(&Ws[st][lr][lk+4], Wg + ko + 4, wok);
            CP_COMMIT();
            CP_WAIT(1);
        } else {
            CP_WAIT(0);
        }
        __syncthreads();
        int st = t & 1;
        #pragma unroll
        for (int ks = 0; ks < 2; ks++) {
            int kb = ks << 3;
            int c = kb + (lane & 3);
            unsigned af[4][4], bf[4][2];
            #pragma unroll
            for (int mt = 0; mt < 4; mt++) {
                int r = wm + (mt << 4) + (lane >> 2);
                af[mt][0] = __float_as_uint(As[st][r][c]);
                af[mt][1] = __float_as_uint(As[st][r+8][c]);
                af[mt][2] = __float_as_uint(As[st][r][c+4]);
                af[mt][3] = __float_as_uint(As[st][r+8][c+4]);
            }
            #pragma unroll
            for (int nt = 0; nt < 4; nt++) {
                int n = wn + (nt << 3) + (lane >> 2);
                bf[nt][0] = __float_as_uint(Ws[st][n][c]);
                bf[nt][1] = __float_as_uint(Ws[st][n][c+4]);
            }
            #pragma unroll
            for (int mt = 0; mt < 4; mt++)
                #pragma unroll
                for (int nt = 0; nt < 4; nt++)
                    mma8(acc[mt][nt], af[mt], bf[nt]);
        }
        __syncthreads();
    }

    #pragma unroll
    for (int mt = 0; mt < 4; mt++) {
        int r0 = bm + wm + (mt << 4) + (lane >> 2);
        #pragma unroll
        for (int nt = 0; nt < 4; nt++) {
            int c0 = bn + wn + (nt << 3) + ((lane & 3) << 1);
            #pragma unroll
            for (int q = 0; q < 4; q++) {
                int r = r0 + ((q >> 1) << 3);
                int cc = c0 + (q & 1);
                if (cc >= N) continue;
                float v = acc[mt][nt][q];
                if (EPI == 1) v += res[(size_t)r * N + cc];
                if (EPI == 2) v = tf32r(v / (1.f + expf(-v)));  // silu out feeds next GEMM
                out[(size_t)r * N + cc] = v;
            }
        }
    }
}

// ---------- mamba prep ----------
__global__ void __launch_bounds__(256) prep_kernel(float* __restrict__ zx,
                                                   const float* __restrict__ dtb,
                                                   const float* __restrict__ Alog,
                                                   const float* __restrict__ Bnw,
                                                   const float* __restrict__ Cnw,
                                                   float* __restrict__ xdt,
                                                   float* __restrict__ acum) {
    __shared__ float dts[32];
    __shared__ float red[8];
    int token = blockIdx.x;
    int b = token >> 11, s = token & 2047;
    float* Z = zx + (size_t)token * DPROJ;
    int tid = threadIdx.x;
    if (tid < 32) {
        float vraw = Z[4352 + tid] + dtb[tid];
        float dt = (vraw > 20.f) ? vraw : log1pf(expf(vraw));
        dts[tid] = dt;
        acum[(size_t)(b*32 + tid)*2048 + s] = -expf(Alog[tid]) * dt;
    }
    float val = Z[4096 + tid];
    float sq = val * val;
    #pragma unroll
    for (int o = 16; o; o >>= 1) sq += __shfl_xor_sync(0xffffffffu, sq, o);
    if ((tid & 31) == 0) red[tid >> 5] = sq;
    __syncthreads();
    for (int j = tid; j < 2048; j += 256)
        xdt[(size_t)token*2048 + j] = Z[2048 + j] * dts[j >> 6];
    float ss = (tid < 128) ? (red[0]+red[1]+red[2]+red[3]) : (red[4]+red[5]+red[6]+red[7]);
    float scale = rsqrtf(ss * (1.f/128.f) + 1e-5f);
    Z[4096 + tid] = val * scale * ((tid < 128) ? Bnw[tid] : Cnw[tid - 128]);
}

// ---------- per-chunk inclusive cumsum of dA ----------
__global__ void cumsum_kernel(float* __restrict__ acum) {
    __shared__ float a[64];
    int l = threadIdx.x;
    size_t base = ((size_t)(blockIdx.z*32 + blockIdx.y))*2048 + (blockIdx.x << 6);
    a[l] = acum[base + l];
    __syncthreads();
    #pragma unroll
    for (int d = 1; d < 64; d <<= 1) {
        float t = (l >= d) ? a[l-d] : 0.f;
        __syncthreads();
        a[l] += t;
        __syncthreads();
    }
    acum[base + l] = a[l];
}

// ---------- chunk kernel: Y_diag + per-chunk states ----------
__global__ void __launch_bounds__(256) chunk_kernel(const float* __restrict__ zx,
                                                    const float* __restrict__ xdt,
                                                    const float* __restrict__ acum,
                                                    float* __restrict__ states,
                                                    float* __restrict__ y) {
    extern __shared__ float sm[];
    float* Bs = sm;               // 64*129
    float* Cs = Bs + 64*129;      // 64*129
    float* Xs = Cs + 64*129;      // 64*64  [s][p]
    float* Sm = Xs + 4096;        // 64*64  [l][s]
    float* Ac = Sm + 4096;        // 64
    int b = blockIdx.z, h = blockIdx.y, c = blockIdx.x;
    int tid = threadIdx.x;
    int row0 = (b << 11) + (c << 6);

    for (int i = tid; i < 8192; i += 256) {
        int l = i >> 7, n = i & 127;
        const float* Z = zx + (size_t)(row0 + l) * DPROJ;
        Bs[l*129 + n] = Z[4096 + n];
        Cs[l*129 + n] = Z[4224 + n];
    }
    for (int i = tid; i < 4096; i += 256) {
        int s = i >> 6, p = i & 63;
        Xs[i] = xdt[(size_t)(row0 + s)*2048 + h*64 + p];
    }
    if (tid < 64) Ac[tid] = acum[(size_t)((b<<5) + h)*2048 + (c<<6) + tid];
    __syncthreads();

    int tx = tid & 15, ty = tid >> 4;
    {
        float acc[4][4];
        #pragma unroll
        for (int i = 0; i < 4; i++)
            #pragma unroll
            for (int j = 0; j < 4; j++) acc[i][j] = 0.f;
        for (int n = 0; n < 128; n++) {
            float rc[4], rb[4];
            #pragma unroll
            for (int i = 0; i < 4; i++) rc[i] = Cs[(ty*4+i)*129 + n];
            #pragma unroll
            for (int j = 0; j < 4; j++) rb[j] = Bs[(tx*4+j)*129 + n];
            #pragma unroll
            for (int i = 0; i < 4; i++)
                #pragma unroll
                for (int j = 0; j < 4; j++) acc[i][j] += rc[i]*rb[j];
        }
        #pragma unroll
        for (int i = 0; i < 4; i++)
            #pragma unroll
            for (int j = 0; j < 4; j++) {
                int l = ty*4+i, s = tx*4+j;
                Sm[l*64 + s] = (l >= s) ? acc[i][j]*expf(Ac[l]-Ac[s]) : 0.f;
            }
    }
    __syncthreads();
    {
        float acc[4][4];
        #pragma unroll
        for (int i = 0; i < 4; i++)
            #pragma unroll
            for (int j = 0; j < 4; j++) acc[i][j] = 0.f;
        for (int s = 0; s < 64; s++) {
            float rs[4], rx[4];
            #pragma unroll
            for (int i = 0; i < 4; i++) rs[i] = Sm[(ty*4+i)*64 + s];
            #pragma unroll
            for (int j = 0; j < 4; j++) rx[j] = Xs[s*64 + tx*4+j];
            #pragma unroll
            for (int i = 0; i < 4; i++)
                #pragma unroll
                for (int j = 0; j < 4; j++) acc[i][j] += rs[i]*rx[j];
        }
        #pragma unroll
        for (int i = 0; i < 4; i++)
            #pragma unroll
            for (int j = 0; j < 4; j++)
                y[(size_t)(row0 + ty*4+i)*2048 + h*64 + tx*4+j] = acc[i][j];
    }
    float alast = Ac[63];
    for (int i = tid; i < 8192; i += 256) {
        int l = i >> 7, n = i & 127;
        Bs[l*129 + n] *= expf(alast - Ac[l]);
    }
    __syncthreads();
    {
        float acc[4][8];
        #pragma unroll
        for (int i = 0; i < 4; i++)
            #pragma unroll
            for (int j = 0; j < 8; j++) acc[i][j] = 0.f;
        for (int l = 0; l < 64; l++) {
            float rx[4], rb[8];
            #pragma unroll
            for (int i = 0; i < 4; i++) rx[i] = Xs[l*64 + ty*4+i];
            #pragma unroll
            for (int j = 0; j < 8; j++) rb[j] = Bs[l*129 + tx*8+j];
            #pragma unroll
            for (int i = 0; i < 4; i++)
                #pragma unroll
                for (int j = 0; j < 8; j++) acc[i][j] += rx[i]*rb[j];
        }
        size_t base = ((size_t)((b*32 + c)*32 + h)) * 8192;
        #pragma unroll
        for (int i = 0; i < 4; i++)
            #pragma unroll
            for (int j = 0; j < 8; j++)
                states[base + (ty*4+i)*128 + tx*8+j] = acc[i][j];
    }
}

// ---------- inter-chunk scan ----------
__global__ void __launch_bounds__(256) scan_kernel(float* __restrict__ states,
                                                   const float* __restrict__ acum) {
    int bh = blockIdx.x;
    int b = bh >> 5, h = bh & 31;
    int tid = threadIdx.x;
    float st[32];
    #pragma unroll
    for (int r = 0; r < 32; r++) st[r] = 0.f;
    for (int z = 0; z < 32; z++) {
        float ed = expf(acum[(size_t)bh*2048 + z*64 + 63]);
        size_t base = ((size_t)((b*32 + z)*32 + h)) * 8192;
        #pragma unroll
        for (int r = 0; r < 32; r++) {
            size_t idx = base + tid + (r << 8);
            float old = states[idx];
            states[idx] = st[r];
            st[r] = ed*st[r] + old;
        }
    }
}

// ---------- Y_off + D-skip + silu gate (output tf32-rounded: GEMM operand) ----------
__global__ void __launch_bounds__(256) yoff_kernel(const float* __restrict__ zx,
                                                   const float* __restrict__ acum,
                                                   const float* __restrict__ states,
                                                   const float* __restrict__ Dp,
                                                   float* __restrict__ y) {
    extern __shared__ float sm[];
    float* Cs = sm;               // 64*129  [l][n]
    float* NS = Cs + 64*129;      // 64*129  [p][n]
    float* Ac = NS + 64*129;      // 64
    int b = blockIdx.z, h = blockIdx.y, c = blockIdx.x;
    int tid = threadIdx.x;
    int row0 = (b << 11) + (c << 6);
    for (int i = tid; i < 8192; i += 256) {
        int l = i >> 7, n = i & 127;
        Cs[l*129 + n] = zx[(size_t)(row0 + l)*DPROJ + 4224 + n];
    }
    size_t sbase = ((size_t)((b*32 + c)*32 + h)) * 8192;
    for (int i = tid; i < 8192; i += 256)
        NS[(i >> 7)*129 + (i & 127)] = states[sbase + i];
    if (tid < 64) Ac[tid] = acum[(size_t)((b<<5) + h)*2048 + (c<<6) + tid];
    __syncthreads();

    int tx = tid & 15, ty = tid >> 4;
    float acc[4][4];
    #pragma unroll
    for (int i = 0; i < 4; i++)
        #pragma unroll
        for (int j = 0; j < 4; j++) acc[i][j] = 0.f;
    for (int n = 0; n < 128; n++) {
        float rc[4], rn[4];
        #pragma unroll
        for (int i = 0; i < 4; i++) rc[i] = Cs[(ty*4+i)*129 + n];
        #pragma unroll
        for (int j = 0; j < 4; j++) rn[j] = NS[(tx*4+j)*129 + n];
        #pragma unroll
        for (int i = 0; i < 4; i++)
            #pragma unroll
            for (int j = 0; j < 4; j++) acc[i][j] += rc[i]*rn[j];
    }
    float dph = Dp[h];
    #pragma unroll
    for (int i = 0; i < 4; i++) {
        int l = ty*4+i;
        float eA = expf(Ac[l]);
        size_t token = row0 + l;
        const float* Z = zx + token * DPROJ;
        #pragma unroll
        for (int j = 0; j < 4; j++) {
            int p = tx*4+j;
            float xs = Z[2048 + h*64 + p];
            float zg = Z[h*64 + p];
            size_t yi = token*2048 + h*64 + p;
            float v = y[yi] + eA*acc[i][j] + xs*dph;
            v *= zg / (1.f + expf(-zg));
            y[yi] = tf32r(v);
        }
    }
}

// ---------- per-head rmsnorm + rope + optional gain ----------
__global__ void rmsrope_kernel(float* __restrict__ X, int nheads, const float* __restrict__ gain) {
    int token = blockIdx.x;
    int h = blockIdx.y;
    int s = token & (S_ - 1);
    float* p = X + (size_t)token*nheads*64 + (size_t)h*64;
    int lane = threadIdx.x;
    float v0 = p[lane], v1 = p[lane + 32];
    float ss = v0*v0 + v1*v1;
    #pragma unroll
    for (int o = 16; o; o >>= 1) ss += __shfl_xor_sync(0xffffffffu, ss, o);
    float sc = rsqrtf(ss * (1.f/64.f) + 1.1920929e-7f);
    v0 *= sc; v1 *= sc;
    float oth = __shfl_xor_sync(0xffffffffu, v0, 8);
    if (lane < 16) {
        int i = lane & 7;
        float inv = powf(10000.f, -(float)i * 0.125f);
        float f = (float)s * inv;
        float cf = cosf(f), sf = sinf(f);
        v0 = (lane < 8) ? (v0*cf + oth*sf) : (v0*cf - oth*sf);
    }
    if (gain) { float g = gain[h]; v0 *= g; v1 *= g; }
    p[lane] = v0; p[lane + 32] = v1;
}

// ---------- tensor-core causal flash attention, 64-row blocks, GQA 4:1 ----------
__global__ void __launch_bounds__(256) attn_tc(const float* __restrict__ Q,
                                               const float* __restrict__ K,
                                               const float* __restrict__ V,
                                               float* __restrict__ O) {
    extern __shared__ float sm[];
    float* Qs = sm;            // 64*68
    float* Ks = Qs + 4352;     // 64*68 [key][d]
    float* Vt = Ks + 4352;     // 64*68 [d][key]
    float* Ss = Vt + 4352;     // 64*68 [row][key] scores/P
    float* rowm   = Ss + 4352; // 64
    float* rowl   = rowm + 64; // 64
    float* ralpha = rowl + 64; // 64
    int b = blockIdx.z, h = blockIdx.y;
    int qt = 31 - blockIdx.x;           // big tiles first
    int tid = threadIdx.x;
    int lane = tid & 31, wid = tid >> 5;
    int mt = (wid & 3) << 4;            // 0,16,32,48
    int nh = (wid >> 2) << 5;           // 0 or 32
    int kvh = h >> 2;
    int r0 = mt + (lane >> 2);

    for (int i = tid; i < 4096; i += 256) {
        int r = i >> 6, c = i & 63;
        Qs[r*68 + c] = Q[(size_t)((b<<11) + (qt<<6) + r)*1024 + h*64 + c];
    }
    if (tid < 64) { rowm[tid] = -1e30f; rowl[tid] = 0.f; }

    float o[4][4];
    #pragma unroll
    for (int nt = 0; nt < 4; nt++)
        #pragma unroll
        for (int q = 0; q < 4; q++) o[nt][q] = 0.f;

    for (int kt = 0; kt <= qt; kt++) {
        __syncthreads();
        for (int i = tid; i < 4096; i += 256) {
            int rr = i >> 6, cc = i & 63;
            size_t idx = (size_t)((b<<11) + (kt<<6) + rr)*256 + kvh*64 + cc;
            Ks[rr*68 + cc] = K[idx];
            Vt[cc*68 + rr] = V[idx];
        }
        __syncthreads();

        float sf[4][4];
        #pragma unroll
        for (int nt = 0; nt < 4; nt++)
            #pragma unroll
            for (int q = 0; q < 4; q++) sf[nt][q] = 0.f;
        #pragma unroll
        for (int k8 = 0; k8 < 8; k8++) {
            int c = (k8 << 3) + (lane & 3);
            unsigned af[4];
            af[0] = f2tf32(Qs[r0*68 + c]);
            af[1] = f2tf32(Qs[(r0+8)*68 + c]);
            af[2] = f2tf32(Qs[r0*68 + c + 4]);
            af[3] = f2tf32(Qs[(r0+8)*68 + c + 4]);
            #pragma unroll
            for (int nt = 0; nt < 4; nt++) {
                int n = nh + (nt << 3) + (lane >> 2);
                unsigned bf[2] = { f2tf32(Ks[n*68 + c]), f2tf32(Ks[n*68 + c + 4]) };
                mma8(sf[nt], af, bf);
            }
        }
        #pragma unroll
        for (int nt = 0; nt < 4; nt++) {
            int c0 = nh + (nt << 3) + ((lane & 3) << 1);
            #pragma unroll
            for (int q = 0; q < 4; q++) {
                int rr = r0 + ((q >> 1) << 3);
                int cc = c0 + (q & 1);
                float s = sf[nt][q] * 0.125f;
                if (kt == qt && cc > rr) s = -1e30f;
                Ss[rr*68 + cc] = s;
            }
        }
        __syncthreads();

        {
            int sr = tid >> 2, scol = (tid & 3) << 4;
            float mloc = -1e30f;
            #pragma unroll
            for (int j = 0; j < 16; j++) mloc = fmaxf(mloc, Ss[sr*68 + scol + j]);
            mloc = fmaxf(mloc, __shfl_xor_sync(0xffffffffu, mloc, 1));
            mloc = fmaxf(mloc, __shfl_xor_sync(0xffffffffu, mloc, 2));
            float mold = rowm[sr];
            float newm = fmaxf(mold, mloc);
            float suml = 0.f;
            #pragma unroll
            for (int j = 0; j < 16; j++) {
                float p = expf(Ss[sr*68 + scol + j] - newm);
                Ss[sr*68 + scol + j] = p;
                suml += p;
            }
            suml += __shfl_xor_sync(0xffffffffu, suml, 1);
            suml += __shfl_xor_sync(0xffffffffu, suml, 2);
            if ((tid & 3) == 0) {
                float a = expf(mold - newm);
                ralpha[sr] = a;
                rowm[sr] = newm;
                rowl[sr] = a * rowl[sr] + suml;
            }
        }
        __syncthreads();

        float a0 = ralpha[r0], a1 = ralpha[r0 + 8];
        #pragma unroll
        for (int nt = 0; nt < 4; nt++) {
            o[nt][0] *= a0; o[nt][1] *= a0;
            o[nt][2] *= a1; o[nt][3] *= a1;
        }
        #pragma unroll
        for (int k8 = 0; k8 < 8; k8++) {
            int c = (k8 << 3) + (lane & 3);
            unsigned af[4];
            af[0] = f2tf32(Ss[r0*68 + c]);
            af[1] = f2tf32(Ss[(r0+8)*68 + c]);
            af[2] = f2tf32(Ss[r0*68 + c + 4]);
            af[3] = f2tf32(Ss[(r0+8)*68 + c + 4]);
            #pragma unroll
            for (int nt = 0; nt < 4; nt++) {
                int n = nh + (nt << 3) + (lane >> 2);
                unsigned bf[2] = { f2tf32(Vt[n*68 + c]), f2tf32(Vt[n*68 + c + 4]) };
                mma8(o[nt], af, bf);
            }
        }
    }

    float l0 = 1.f / rowl[r0], l1 = 1.f / rowl[r0 + 8];
    #pragma unroll
    for (int nt = 0; nt < 4; nt++) {
        int c0 = nh + (nt << 3) + ((lane & 3) << 1);
        #pragma unroll
        for (int q = 0; q < 4; q++) {
            int rr = r0 + ((q >> 1) << 3);
            int cc = c0 + (q & 1);
            O[(size_t)((b<<11) + (qt<<6) + rr)*1024 + h*64 + cc] =
                tf32r(o[nt][q] * ((q < 2) ? l0 : l1));   // feeds cproj GEMM
        }
    }
}

// ---------- launch ----------
extern "C" void kernel_launch(void* const* d_in, const int* in_sizes, int n_in,
                              void* d_out, int out_size) {
    const float* x     = (const float*)d_in[0];
    const float* mnw   = (const float*)d_in[1];
    const float* inw   = (const float*)d_in[2];
    const float* outw  = (const float*)d_in[3];
    const float* Dp    = (const float*)d_in[4];
    const float* dtb   = (const float*)d_in[5];
    const float* Alog  = (const float*)d_in[6];
    const float* Bnw   = (const float*)d_in[7];
    const float* Cnw   = (const float*)d_in[8];
    const float* ln1w  = (const float*)d_in[9];
    const float* ln1b  = (const float*)d_in[10];
    const float* cqw   = (const float*)d_in[11];
    const float* ckw   = (const float*)d_in[12];
    const float* cvw   = (const float*)d_in[13];
    const float* cpw   = (const float*)d_in[14];
    const float* qg    = (const float*)d_in[15];
    const float* ln2w  = (const float*)d_in[16];
    const float* ln2b  = (const float*)d_in[17];
    const float* fcw   = (const float*)d_in[18];
    const float* pjw   = (const float*)d_in[19];
    float* out = (float*)d_out;

    float* S = nullptr;
    cudaGetSymbolAddress((void**)&S, g_scratch);
    float* h      = S + OFF_H;
    float* zx     = S + OFF_ZX;
    float* acum   = S + OFF_ACUM;
    float* xdt    = S + OFF_XDT;
    float* states = S + OFF_STATES;
    float* y      = S + OFF_Y;
    float* x1     = S + OFF_X1;
    float* q      = S + OFF_Q;
    float* k      = S + OFF_K;
    float* v      = S + OFF_V;
    float* ao     = S + OFF_AO;
    float* x2     = S + OFF_X2;
    float* mlp    = S + OFF_MLP;

    // tf32-rounded weights in scratch
    float* winw  = S + OFF_WC;
    float* woutw = winw  + 4489216;
    float* wcqw  = woutw + 2097152;
    float* wckw  = wcqw  + 1048576;
    float* wcvw  = wckw  + 262144;
    float* wcpw  = wcvw  + 262144;
    float* wfcw  = wcpw  + 1048576;
    float* wpjw  = wfcw  + 3145728;

    const int CH_SMEM = (2*64*129 + 2*4096 + 64) * 4;
    const int YO_SMEM = (2*64*129 + 64) * 4;
    const int AT_SMEM = (4*4352 + 192) * 4;  // 70400 B
    cudaFuncSetAttribute(chunk_kernel, cudaFuncAttributeMaxDynamicSharedMemorySize, CH_SMEM);
    cudaFuncSetAttribute(yoff_kernel,  cudaFuncAttributeMaxDynamicSharedMemorySize, YO_SMEM);
    cudaFuncSetAttribute(attn_tc,      cudaFuncAttributeMaxDynamicSharedMemorySize, AT_SMEM);

    // ===== weight tf32 pre-rounding =====
    #define CVTW(dst, src, n) cvtw_kernel<<<((n)/4 + 255)/256, 256>>>((const float4*)(src), (float4*)(dst), (n)/4)
    CVTW(winw,  inw,  4489216);
    CVTW(woutw, outw, 2097152);
    CVTW(wcqw,  cqw,  1048576);
    CVTW(wckw,  ckw,  262144);
    CVTW(wcvw,  cvw,  262144);
    CVTW(wcpw,  cpw,  1048576);
    CVTW(wfcw,  fcw,  3145728);
    CVTW(wpjw,  pjw,  3145728);
    #undef CVTW

    // ===== Mamba block =====
    rmsnorm_kernel<<<4096, 256>>>(x, mnw, h);
    gemm_tc<0><<<dim3(35, 32), 256>>>(h, winw, nullptr, zx, 4096, 4384, 1024);
    prep_kernel<<<4096, 256>>>(zx, dtb, Alog, Bnw, Cnw, xdt, acum);
    cumsum_kernel<<<dim3(32, 32, 2), 64>>>(acum);
    chunk_kernel<<<dim3(32, 32, 2), 256, CH_SMEM>>>(zx, xdt, acum, states, y);
    scan_kernel<<<64, 256>>>(states, acum);
    yoff_kernel<<<dim3(32, 32, 2), 256, YO_SMEM>>>(zx, acum, states, Dp, y);
    gemm_tc<1><<<dim3(8, 32), 256>>>(y, woutw, x, x1, 4096, 1024, 2048);

    // ===== Attention block =====
    layernorm_kernel<<<4096, 256>>>(x1, ln1w, ln1b, h);
    gemm_tc<0><<<dim3(8, 32), 256>>>(h, wcqw, nullptr, q, 4096, 1024, 1024);
    gemm_tc<0><<<dim3(2, 32), 256>>>(h, wckw, nullptr, k, 4096, 256, 1024);
    gemm_tc<0><<<dim3(2, 32), 256>>>(h, wcvw, nullptr, v, 4096, 256, 1024);
    rmsrope_kernel<<<dim3(4096, 16), 32>>>(q, 16, qg);
    rmsrope_kernel<<<dim3(4096, 4), 32>>>(k, 4, nullptr);
    attn_tc<<<dim3(32, 16, 2), 256, AT_SMEM>>>(q, k, v, ao);
    gemm_tc<1><<<dim3(8, 32), 256>>>(ao, wcpw, x1, x2, 4096, 1024, 1024);

    // ===== MLP =====
    layernorm_kernel<<<4096, 256>>>(x2, ln2w, ln2b, h);
    gemm_tc<2><<<dim3(24, 32), 256>>>(h, wfcw, nullptr, mlp, 4096, 3072, 1024);
    gemm_tc<1><<<dim3(8, 32), 256>>>(mlp, wpjw, x2, out, 4096, 1024, 3072);
}

// round 14
// speedup vs baseline: 1.2023x; 1.2023x over previous
#include <cuda_runtime.h>
#include <cuda_bf16.h>
#include <cstdint>
#include <math.h>

#define S_ 2048
#define DPROJ 4384

// ---------- scratch (floats) ----------
#define OFF_H        0ull
#define OFF_ZX       (OFF_H      + 4194304ull)   // 4096*1024
#define OFF_ACUM     (OFF_ZX     + 17956864ull)  // 4096*4384
#define OFF_XDT      (OFF_ACUM   + 131072ull)    // 64*2048
#define OFF_STATES   (OFF_XDT    + 8388608ull)   // 4096*2048
#define OFF_Y        (OFF_STATES + 16777216ull)  // 2*32*32*64*128
#define OFF_X1       (OFF_Y      + 8388608ull)
#define OFF_Q        (OFF_X1     + 4194304ull)
#define OFF_K        (OFF_Q      + 4194304ull)
#define OFF_V        (OFF_K      + 1048576ull)
#define OFF_AO       (OFF_V      + 1048576ull)
#define OFF_X2       (OFF_AO     + 4194304ull)
#define OFF_MLP      (OFF_X2     + 4194304ull)
#define SCRATCH_FLOATS (OFF_MLP + 12582912ull)

__device__ float g_scratch[SCRATCH_FLOATS];

// ---------- helpers ----------
__device__ __forceinline__ float bsum256(float v, float* red) {
    #pragma unroll
    for (int o = 16; o; o >>= 1) v += __shfl_xor_sync(0xffffffffu, v, o);
    if ((threadIdx.x & 31) == 0) red[threadIdx.x >> 5] = v;
    __syncthreads();
    float t = red[0]+red[1]+red[2]+red[3]+red[4]+red[5]+red[6]+red[7];
    __syncthreads();
    return t;
}

__device__ __forceinline__ unsigned f2tf32(float f) {
    unsigned r; asm("cvt.rna.tf32.f32 %0, %1;" : "=r"(r) : "f"(f)); return r;
}

__device__ __forceinline__ void cp16(float* s, const float* g, bool p) {
    unsigned sa = (unsigned)__cvta_generic_to_shared(s);
    int sz = p ? 16 : 0;
    asm volatile("cp.async.cg.shared.global [%0], [%1], 16, %2;" :: "r"(sa), "l"(g), "r"(sz));
}
#define CP_COMMIT() asm volatile("cp.async.commit_group;")
#define CP_WAIT(N)  asm volatile("cp.async.wait_group %0;" :: "n"(N))

__device__ __forceinline__ void mma8(float* c, const unsigned* a, const unsigned* b) {
    asm volatile("mma.sync.aligned.m16n8k8.row.col.f32.tf32.tf32.f32 "
        "{%0,%1,%2,%3},{%4,%5,%6,%7},{%8,%9},{%0,%1,%2,%3};"
        : "+f"(c[0]), "+f"(c[1]), "+f"(c[2]), "+f"(c[3])
        : "r"(a[0]), "r"(a[1]), "r"(a[2]), "r"(a[3]), "r"(b[0]), "r"(b[1]));
}

// ---------- rmsnorm over 1024 ----------
__global__ void __launch_bounds__(256) rmsnorm_kernel(const float* __restrict__ x,
                                                      const float* __restrict__ w,
                                                      float* __restrict__ out) {
    __shared__ float red[8];
    size_t row = blockIdx.x;
    const float* xr = x + (row << 10);
    float v[4]; float ss = 0.f;
    #pragma unroll
    for (int i = 0; i < 4; i++) { v[i] = xr[threadIdx.x + (i << 8)]; ss += v[i]*v[i]; }
    float tot = bsum256(ss, red);
    float sc = rsqrtf(tot * (1.f/1024.f) + 1e-5f);
    float* orow = out + (row << 10);
    #pragma unroll
    for (int i = 0; i < 4; i++) {
        int j = threadIdx.x + (i << 8);
        orow[j] = v[i] * sc * w[j];
    }
}

// ---------- layernorm over 1024 ----------
__global__ void __launch_bounds__(256) layernorm_kernel(const float* __restrict__ x,
                                                        const float* __restrict__ w,
                                                        const float* __restrict__ bb,
                                                        float* __restrict__ out) {
    __shared__ float red[8];
    size_t row = blockIdx.x;
    const float* xr = x + (row << 10);
    float v[4]; float s = 0.f;
    #pragma unroll
    for (int i = 0; i < 4; i++) { v[i] = xr[threadIdx.x + (i << 8)]; s += v[i]; }
    float mean = bsum256(s, red) * (1.f/1024.f);
    float sv = 0.f;
    #pragma unroll
    for (int i = 0; i < 4; i++) { float d = v[i]-mean; sv += d*d; }
    float var = bsum256(sv, red) * (1.f/1024.f);
    float sc = rsqrtf(var + 1e-5f);
    float* orow = out + (row << 10);
    #pragma unroll
    for (int i = 0; i < 4; i++) {
        int j = threadIdx.x + (i << 8);
        orow[j] = (v[i]-mean)*sc*w[j] + bb[j];
    }
}

// ---------- tensor-core TF32 GEMM (R9 structure, unchanged) ----------
template<int EPI>
__global__ void __launch_bounds__(256) gemm_tc(const float* __restrict__ A,
                                               const float* __restrict__ W,
                                               const float* __restrict__ res,
                                               float* __restrict__ out,
                                               int M, int N, int K) {
    __shared__ float As[2][128][20];
    __shared__ float Ws[2][128][20];
    int tid = threadIdx.x;
    int bm = blockIdx.y << 7, bn = blockIdx.x << 7;
    int lane = tid & 31, wid = tid >> 5;
    int wm = (wid & 1) << 6;
    int wn = (wid >> 1) << 5;

    int lr = tid >> 1;
    int lk = (tid & 1) << 3;
    const float* Ag = A + (size_t)(bm + lr) * K + lk;
    int wrow = bn + lr;
    bool wok = wrow < N;
    const float* Wg = W + (size_t)(wok ? wrow : (N-1)) * K + lk;

    float acc[4][4][4];
    #pragma unroll
    for (int i = 0; i < 4; i++)
        #pragma unroll
        for (int j = 0; j < 4; j++)
            #pragma unroll
            for (int q = 0; q < 4; q++) acc[i][j][q] = 0.f;

    int nk = K >> 4;
    cp16(&As[0][lr][lk],   Ag,     true);
    cp16(&As[0][lr][lk+4], Ag + 4, true);
    cp16(&Ws[0][lr][lk],   Wg,     wok);
    cp16(&Ws[0][lr][lk+4], Wg + 4, wok);
    CP_COMMIT();

    for (int t = 0; t < nk; t++) {
        if (t + 1 < nk) {
            int st = (t + 1) & 1;
            int ko = (t + 1) << 4;
            cp16(&As[st][lr][lk],   Ag + ko,     true);
            cp16(&As[st][lr][lk+4], Ag + ko + 4, true);
            cp16(&Ws[st][lr][lk],   Wg + ko,     wok);
            cp16(&Ws[st][lr][lk+4], Wg + ko + 4, wok);
            CP_COMMIT();
            CP_WAIT(1);
        } else {
            CP_WAIT(0);
        }
        __syncthreads();
        int st = t & 1;
        #pragma unroll
        for (int ks = 0; ks < 2; ks++) {
            int kb = ks << 3;
            int c = kb + (lane & 3);
            unsigned af[4][4], bf[4][2];
            #pragma unroll
            for (int mt = 0; mt < 4; mt++) {
                int r = wm + (mt << 4) + (lane >> 2);
                af[mt][0] = f2tf32(As[st][r][c]);
                af[mt][1] = f2tf32(As[st][r+8][c]);
                af[mt][2] = f2tf32(As[st][r][c+4]);
                af[mt][3] = f2tf32(As[st][r+8][c+4]);
            }
            #pragma unroll
            for (int nt = 0; nt < 4; nt++) {
                int n = wn + (nt << 3) + (lane >> 2);
                bf[nt][0] = f2tf32(Ws[st][n][c]);
                bf[nt][1] = f2tf32(Ws[st][n][c+4]);
            }
            #pragma unroll
            for (int mt = 0; mt < 4; mt++)
                #pragma unroll
                for (int nt = 0; nt < 4; nt++)
                    mma8(acc[mt][nt], af[mt], bf[nt]);
        }
        __syncthreads();
    }

    #pragma unroll
    for (int mt = 0; mt < 4; mt++) {
        int r0 = bm + wm + (mt << 4) + (lane >> 2);
        #pragma unroll
        for (int nt = 0; nt < 4; nt++) {
            int c0 = bn + wn + (nt << 3) + ((lane & 3) << 1);
            #pragma unroll
            for (int q = 0; q < 4; q++) {
                int r = r0 + ((q >> 1) << 3);
                int cc = c0 + (q & 1);
                if (cc >= N) continue;
                float v = acc[mt][nt][q];
                if (EPI == 1) v += res[(size_t)r * N + cc];
                if (EPI == 2) v = v / (1.f + expf(-v));
                out[(size_t)r * N + cc] = v;
            }
        }
    }
}

// ---------- mamba prep ----------
__global__ void __launch_bounds__(256) prep_kernel(float* __restrict__ zx,
                                                   const float* __restrict__ dtb,
                                                   const float* __restrict__ Alog,
                                                   const float* __restrict__ Bnw,
                                                   const float* __restrict__ Cnw,
                                                   float* __restrict__ xdt,
                                                   float* __restrict__ acum) {
    __shared__ float dts[32];
    __shared__ float red[8];
    int token = blockIdx.x;
    int b = token >> 11, s = token & 2047;
    float* Z = zx + (size_t)token * DPROJ;
    int tid = threadIdx.x;
    if (tid < 32) {
        float vraw = Z[4352 + tid] + dtb[tid];
        float dt = (vraw > 20.f) ? vraw : log1pf(expf(vraw));
        dts[tid] = dt;
        acum[(size_t)(b*32 + tid)*2048 + s] = -expf(Alog[tid]) * dt;
    }
    float val = Z[4096 + tid];
    float sq = val * val;
    #pragma unroll
    for (int o = 16; o; o >>= 1) sq += __shfl_xor_sync(0xffffffffu, sq, o);
    if ((tid & 31) == 0) red[tid >> 5] = sq;
    __syncthreads();
    for (int j = tid; j < 2048; j += 256)
        xdt[(size_t)token*2048 + j] = Z[2048 + j] * dts[j >> 6];
    float ss = (tid < 128) ? (red[0]+red[1]+red[2]+red[3]) : (red[4]+red[5]+red[6]+red[7]);
    float scale = rsqrtf(ss * (1.f/128.f) + 1e-5f);
    Z[4096 + tid] = val * scale * ((tid < 128) ? Bnw[tid] : Cnw[tid - 128]);
}

// ---------- per-chunk inclusive cumsum of dA ----------
__global__ void cumsum_kernel(float* __restrict__ acum) {
    __shared__ float a[64];
    int l = threadIdx.x;
    size_t base = ((size_t)(blockIdx.z*32 + blockIdx.y))*2048 + (blockIdx.x << 6);
    a[l] = acum[base + l];
    __syncthreads();
    #pragma unroll
    for (int d = 1; d < 64; d <<= 1) {
        float t = (l >= d) ? a[l-d] : 0.f;
        __syncthreads();
        a[l] += t;
        __syncthreads();
    }
    acum[base + l] = a[l];
}

// ---------- chunk kernel: Y_diag + per-chunk states (G matmul on tensor cores) ----------
__global__ void __launch_bounds__(256) chunk_kernel(const float* __restrict__ zx,
                                                    const float* __restrict__ xdt,
                                                    const float* __restrict__ acum,
                                                    float* __restrict__ states,
                                                    float* __restrict__ y) {
    extern __shared__ float sm[];
    float* Bs = sm;               // 64*132  [s][n]
    float* Cs = Bs + 64*132;      // 64*132  [l][n]
    float* Xs = Cs + 64*132;      // 64*64   [s][p]
    float* Sm = Xs + 4096;        // 64*64   [l][s]
    float* Ac = Sm + 4096;        // 64
    int b = blockIdx.z, h = blockIdx.y, c = blockIdx.x;
    int tid = threadIdx.x;
    int row0 = (b << 11) + (c << 6);

    for (int i = tid; i < 8192; i += 256) {
        int l = i >> 7, n = i & 127;
        const float* Z = zx + (size_t)(row0 + l) * DPROJ;
        Bs[l*132 + n] = Z[4096 + n];
        Cs[l*132 + n] = Z[4224 + n];
    }
    for (int i = tid; i < 4096; i += 256) {
        int s = i >> 6, p = i & 63;
        Xs[i] = xdt[(size_t)(row0 + s)*2048 + h*64 + p];
    }
    if (tid < 64) Ac[tid] = acum[(size_t)((b<<5) + h)*2048 + (c<<6) + tid];
    __syncthreads();

    int lane = tid & 31, wid = tid >> 5;
    // ---- G = C B^T via mma (warp = 16 rows x 32 cols), decay-masked into Sm ----
    {
        int mt = (wid & 3) << 4;
        int nh = (wid >> 2) << 5;
        int r0 = mt + (lane >> 2);
        float sf[4][4];
        #pragma unroll
        for (int nt = 0; nt < 4; nt++)
            #pragma unroll
            for (int q = 0; q < 4; q++) sf[nt][q] = 0.f;
        #pragma unroll
        for (int k8 = 0; k8 < 16; k8++) {
            int cc = (k8 << 3) + (lane & 3);
            unsigned af[4];
            af[0] = f2tf32(Cs[r0*132 + cc]);
            af[1] = f2tf32(Cs[(r0+8)*132 + cc]);
            af[2] = f2tf32(Cs[r0*132 + cc + 4]);
            af[3] = f2tf32(Cs[(r0+8)*132 + cc + 4]);
            #pragma unroll
            for (int nt = 0; nt < 4; nt++) {
                int n = nh + (nt << 3) + (lane >> 2);
                unsigned bf[2] = { f2tf32(Bs[n*132 + cc]), f2tf32(Bs[n*132 + cc + 4]) };
                mma8(sf[nt], af, bf);
            }
        }
        #pragma unroll
        for (int nt = 0; nt < 4; nt++) {
            int c0 = nh + (nt << 3) + ((lane & 3) << 1);
            #pragma unroll
            for (int q = 0; q < 4; q++) {
                int rr = r0 + ((q >> 1) << 3);
                int ss = c0 + (q & 1);
                Sm[rr*64 + ss] = (rr >= ss) ? sf[nt][q]*expf(Ac[rr]-Ac[ss]) : 0.f;
            }
        }
    }
    __syncthreads();

    int tx = tid & 15, ty = tid >> 4;
    // ---- Y_diag = Sm @ X (scalar) ----
    {
        float acc[4][4];
        #pragma unroll
        for (int i = 0; i < 4; i++)
            #pragma unroll
            for (int j = 0; j < 4; j++) acc[i][j] = 0.f;
        for (int s = 0; s < 64; s++) {
            float rs[4], rx[4];
            #pragma unroll
            for (int i = 0; i < 4; i++) rs[i] = Sm[(ty*4+i)*64 + s];
            #pragma unroll
            for (int j = 0; j < 4; j++) rx[j] = Xs[s*64 + tx*4+j];
            #pragma unroll
            for (int i = 0; i < 4; i++)
                #pragma unroll
                for (int j = 0; j < 4; j++) acc[i][j] += rs[i]*rx[j];
        }
        #pragma unroll
        for (int i = 0; i < 4; i++)
            #pragma unroll
            for (int j = 0; j < 4; j++)
                y[(size_t)(row0 + ty*4+i)*2048 + h*64 + tx*4+j] = acc[i][j];
    }
    float alast = Ac[63];
    for (int i = tid; i < 8192; i += 256) {
        int l = i >> 7, n = i & 127;
        Bs[l*132 + n] *= expf(alast - Ac[l]);
    }
    __syncthreads();
    // ---- states (scalar) ----
    {
        float acc[4][8];
        #pragma unroll
        for (int i = 0; i < 4; i++)
            #pragma unroll
            for (int j = 0; j < 8; j++) acc[i][j] = 0.f;
        for (int l = 0; l < 64; l++) {
            float rx[4], rb[8];
            #pragma unroll
            for (int i = 0; i < 4; i++) rx[i] = Xs[l*64 + ty*4+i];
            #pragma unroll
            for (int j = 0; j < 8; j++) rb[j] = Bs[l*132 + tx*8+j];
            #pragma unroll
            for (int i = 0; i < 4; i++)
                #pragma unroll
                for (int j = 0; j < 8; j++) acc[i][j] += rx[i]*rb[j];
        }
        size_t base = ((size_t)((b*32 + c)*32 + h)) * 8192;
        #pragma unroll
        for (int i = 0; i < 4; i++)
            #pragma unroll
            for (int j = 0; j < 8; j++)
                states[base + (ty*4+i)*128 + tx*8+j] = acc[i][j];
    }
}

// ---------- inter-chunk scan (widened: 256 blocks) ----------
__global__ void __launch_bounds__(256) scan_kernel(float* __restrict__ states,
                                                   const float* __restrict__ acum) {
    int bh = blockIdx.x;
    int b = bh >> 5, h = bh & 31;
    int sl = blockIdx.y;   // 0..3, covers rows sl*8 .. sl*8+7 of 32
    int tid = threadIdx.x;
    float st[8];
    #pragma unroll
    for (int r = 0; r < 8; r++) st[r] = 0.f;
    for (int z = 0; z < 32; z++) {
        float ed = expf(acum[(size_t)bh*2048 + z*64 + 63]);
        size_t base = ((size_t)((b*32 + z)*32 + h)) * 8192;
        #pragma unroll
        for (int r = 0; r < 8; r++) {
            size_t idx = base + tid + ((sl*8 + r) << 8);
            float old = states[idx];
            states[idx] = st[r];
            st[r] = ed*st[r] + old;
        }
    }
}

// ---------- Y_off + D-skip + silu gate (matmul on tensor cores) ----------
__global__ void __launch_bounds__(256) yoff_kernel(const float* __restrict__ zx,
                                                   const float* __restrict__ acum,
                                                   const float* __restrict__ states,
                                                   const float* __restrict__ Dp,
                                                   float* __restrict__ y) {
    extern __shared__ float sm[];
    float* Cs = sm;               // 64*132  [l][n]
    float* NS = Cs + 64*132;      // 64*132  [p][n]
    float* Ac = NS + 64*132;      // 64
    int b = blockIdx.z, h = blockIdx.y, c = blockIdx.x;
    int tid = threadIdx.x;
    int row0 = (b << 11) + (c << 6);
    for (int i = tid; i < 8192; i += 256) {
        int l = i >> 7, n = i & 127;
        Cs[l*132 + n] = zx[(size_t)(row0 + l)*DPROJ + 4224 + n];
    }
    size_t sbase = ((size_t)((b*32 + c)*32 + h)) * 8192;
    for (int i = tid; i < 8192; i += 256)
        NS[(i >> 7)*132 + (i & 127)] = states[sbase + i];
    if (tid < 64) Ac[tid] = acum[(size_t)((b<<5) + h)*2048 + (c<<6) + tid];
    __syncthreads();

    int lane = tid & 31, wid = tid >> 5;
    int mt = (wid & 3) << 4;
    int nh = (wid >> 2) << 5;
    int r0 = mt + (lane >> 2);
    float sf[4][4];
    #pragma unroll
    for (int nt = 0; nt < 4; nt++)
        #pragma unroll
        for (int q = 0; q < 4; q++) sf[nt][q] = 0.f;
    #pragma unroll
    for (int k8 = 0; k8 < 16; k8++) {
        int cc = (k8 << 3) + (lane & 3);
        unsigned af[4];
        af[0] = f2tf32(Cs[r0*132 + cc]);
        af[1] = f2tf32(Cs[(r0+8)*132 + cc]);
        af[2] = f2tf32(Cs[r0*132 + cc + 4]);
        af[3] = f2tf32(Cs[(r0+8)*132 + cc + 4]);
        #pragma unroll
        for (int nt = 0; nt < 4; nt++) {
            int n = nh + (nt << 3) + (lane >> 2);
            unsigned bf[2] = { f2tf32(NS[n*132 + cc]), f2tf32(NS[n*132 + cc + 4]) };
            mma8(sf[nt], af, bf);
        }
    }
    float dph = Dp[h];
    #pragma unroll
    for (int nt = 0; nt < 4; nt++) {
        int c0 = nh + (nt << 3) + ((lane & 3) << 1);
        #pragma unroll
        for (int q = 0; q < 4; q++) {
            int l = r0 + ((q >> 1) << 3);
            int p = c0 + (q & 1);
            float eA = expf(Ac[l]);
            size_t token = row0 + l;
            const float* Z = zx + token * DPROJ;
            float xs = Z[2048 + h*64 + p];
            float zg = Z[h*64 + p];
            size_t yi = token*2048 + h*64 + p;
            float v = y[yi] + eA*sf[nt][q] + xs*dph;
            v *= zg / (1.f + expf(-zg));
            y[yi] = v;
        }
    }
}

// ---------- per-head rmsnorm + rope + optional gain ----------
__global__ void rmsrope_kernel(float* __restrict__ X, int nheads, const float* __restrict__ gain) {
    int token = blockIdx.x;
    int h = blockIdx.y;
    int s = token & (S_ - 1);
    float* p = X + (size_t)token*nheads*64 + (size_t)h*64;
    int lane = threadIdx.x;
    float v0 = p[lane], v1 = p[lane + 32];
    float ss = v0*v0 + v1*v1;
    #pragma unroll
    for (int o = 16; o; o >>= 1) ss += __shfl_xor_sync(0xffffffffu, ss, o);
    float sc = rsqrtf(ss * (1.f/64.f) + 1.1920929e-7f);
    v0 *= sc; v1 *= sc;
    float oth = __shfl_xor_sync(0xffffffffu, v0, 8);
    if (lane < 16) {
        int i = lane & 7;
        float inv = powf(10000.f, -(float)i * 0.125f);
        float f = (float)s * inv;
        float cf = cosf(f), sf = sinf(f);
        v0 = (lane < 8) ? (v0*cf + oth*sf) : (v0*cf - oth*sf);
    }
    if (gain) { float g = gain[h]; v0 *= g; v1 *= g; }
    p[lane] = v0; p[lane + 32] = v1;
}

// ---------- tensor-core causal flash attention, 64-row blocks, GQA 4:1 ----------
__global__ void __launch_bounds__(256) attn_tc(const float* __restrict__ Q,
                                               const float* __restrict__ K,
                                               const float* __restrict__ V,
                                               float* __restrict__ O) {
    extern __shared__ float sm[];
    float* Qs = sm;            // 64*68
    float* Ks = Qs + 4352;     // 64*68 [key][d]
    float* Vt = Ks + 4352;     // 64*68 [d][key]
    float* Ss = Vt + 4352;     // 64*68 [row][key] scores/P
    float* rowm   = Ss + 4352; // 64
    float* rowl   = rowm + 64; // 64
    float* ralpha = rowl + 64; // 64
    int b = blockIdx.z, h = blockIdx.y;
    int qt = 31 - blockIdx.x;           // big tiles first
    int tid = threadIdx.x;
    int lane = tid & 31, wid = tid >> 5;
    int mt = (wid & 3) << 4;            // 0,16,32,48
    int nh = (wid >> 2) << 5;           // 0 or 32
    int kvh = h >> 2;
    int r0 = mt + (lane >> 2);

    for (int i = tid; i < 4096; i += 256) {
        int r = i >> 6, c = i & 63;
        Qs[r*68 + c] = Q[(size_t)((b<<11) + (qt<<6) + r)*1024 + h*64 + c];
    }
    if (tid < 64) { rowm[tid] = -1e30f; rowl[tid] = 0.f; }

    float o[4][4];
    #pragma unroll
    for (int nt = 0; nt < 4; nt++)
        #pragma unroll
        for (int q = 0; q < 4; q++) o[nt][q] = 0.f;

    for (int kt = 0; kt <= qt; kt++) {
        __syncthreads();
        for (int i = tid; i < 4096; i += 256) {
            int rr = i >> 6, cc = i & 63;
            size_t idx = (size_t)((b<<11) + (kt<<6) + rr)*256 + kvh*64 + cc;
            Ks[rr*68 + cc] = K[idx];
            Vt[cc*68 + rr] = V[idx];
        }
        __syncthreads();

        float sf[4][4];
        #pragma unroll
        for (int nt = 0; nt < 4; nt++)
            #pragma unroll
            for (int q = 0; q < 4; q++) sf[nt][q] = 0.f;
        #pragma unroll
        for (int k8 = 0; k8 < 8; k8++) {
            int c = (k8 << 3) + (lane & 3);
            unsigned af[4];
            af[0] = f2tf32(Qs[r0*68 + c]);
            af[1] = f2tf32(Qs[(r0+8)*68 + c]);
            af[2] = f2tf32(Qs[r0*68 + c + 4]);
            af[3] = f2tf32(Qs[(r0+8)*68 + c + 4]);
            #pragma unroll
            for (int nt = 0; nt < 4; nt++) {
                int n = nh + (nt << 3) + (lane >> 2);
                unsigned bf[2] = { f2tf32(Ks[n*68 + c]), f2tf32(Ks[n*68 + c + 4]) };
                mma8(sf[nt], af, bf);
            }
        }
        #pragma unroll
        for (int nt = 0; nt < 4; nt++) {
            int c0 = nh + (nt << 3) + ((lane & 3) << 1);
            #pragma unroll
            for (int q = 0; q < 4; q++) {
                int rr = r0 + ((q >> 1) << 3);
                int cc = c0 + (q & 1);
                float s = sf[nt][q] * 0.125f;
                if (kt == qt && cc > rr) s = -1e30f;
                Ss[rr*68 + cc] = s;
            }
        }
        __syncthreads();

        {
            int sr = tid >> 2, scol = (tid & 3) << 4;
            float mloc = -1e30f;
            #pragma unroll
            for (int j = 0; j < 16; j++) mloc = fmaxf(mloc, Ss[sr*68 + scol + j]);
            mloc = fmaxf(mloc, __shfl_xor_sync(0xffffffffu, mloc, 1));
            mloc = fmaxf(mloc, __shfl_xor_sync(0xffffffffu, mloc, 2));
            float mold = rowm[sr];
            float newm = fmaxf(mold, mloc);
            float suml = 0.f;
            #pragma unroll
            for (int j = 0; j < 16; j++) {
                float p = expf(Ss[sr*68 + scol + j] - newm);
                Ss[sr*68 + scol + j] = p;
                suml += p;
            }
            suml += __shfl_xor_sync(0xffffffffu, suml, 1);
            suml += __shfl_xor_sync(0xffffffffu, suml, 2);
            if ((tid & 3) == 0) {
                float a = expf(mold - newm);
                ralpha[sr] = a;
                rowm[sr] = newm;
                rowl[sr] = a * rowl[sr] + suml;
            }
        }
        __syncthreads();

        float a0 = ralpha[r0], a1 = ralpha[r0 + 8];
        #pragma unroll
        for (int nt = 0; nt < 4; nt++) {
            o[nt][0] *= a0; o[nt][1] *= a0;
            o[nt][2] *= a1; o[nt][3] *= a1;
        }
        #pragma unroll
        for (int k8 = 0; k8 < 8; k8++) {
            int c = (k8 << 3) + (lane & 3);
            unsigned af[4];
            af[0] = f2tf32(Ss[r0*68 + c]);
            af[1] = f2tf32(Ss[(r0+8)*68 + c]);
            af[2] = f2tf32(Ss[r0*68 + c + 4]);
            af[3] = f2tf32(Ss[(r0+8)*68 + c + 4]);
            #pragma unroll
            for (int nt = 0; nt < 4; nt++) {
                int n = nh + (nt << 3) + (lane >> 2);
                unsigned bf[2] = { f2tf32(Vt[n*68 + c]), f2tf32(Vt[n*68 + c + 4]) };
                mma8(o[nt], af, bf);
            }
        }
    }

    float l0 = 1.f / rowl[r0], l1 = 1.f / rowl[r0 + 8];
    #pragma unroll
    for (int nt = 0; nt < 4; nt++) {
        int c0 = nh + (nt << 3) + ((lane & 3) << 1);
        #pragma unroll
        for (int q = 0; q < 4; q++) {
            int rr = r0 + ((q >> 1) << 3);
            int cc = c0 + (q & 1);
            O[(size_t)((b<<11) + (qt<<6) + rr)*1024 + h*64 + cc] =
                o[nt][q] * ((q < 2) ? l0 : l1);
        }
    }
}

// ---------- launch ----------
extern "C" void kernel_launch(void* const* d_in, const int* in_sizes, int n_in,
                              void* d_out, int out_size) {
    const float* x     = (const float*)d_in[0];
    const float* mnw   = (const float*)d_in[1];
    const float* inw   = (const float*)d_in[2];
    const float* outw  = (const float*)d_in[3];
    const float* Dp    = (const float*)d_in[4];
    const float* dtb   = (const float*)d_in[5];
    const float* Alog  = (const float*)d_in[6];
    const float* Bnw   = (const float*)d_in[7];
    const float* Cnw   = (const float*)d_in[8];
    const float* ln1w  = (const float*)d_in[9];
    const float* ln1b  = (const float*)d_in[10];
    const float* cqw   = (const float*)d_in[11];
    const float* ckw   = (const float*)d_in[12];
    const float* cvw   = (const float*)d_in[13];
    const float* cpw   = (const float*)d_in[14];
    const float* qg    = (const float*)d_in[15];
    const float* ln2w  = (const float*)d_in[16];
    const float* ln2b  = (const float*)d_in[17];
    const float* fcw   = (const float*)d_in[18];
    const float* pjw   = (const float*)d_in[19];
    float* out = (float*)d_out;

    float* S = nullptr;
    cudaGetSymbolAddress((void**)&S, g_scratch);
    float* h      = S + OFF_H;
    float* zx     = S + OFF_ZX;
    float* acum   = S + OFF_ACUM;
    float* xdt    = S + OFF_XDT;
    float* states = S + OFF_STATES;
    float* y      = S + OFF_Y;
    float* x1     = S + OFF_X1;
    float* q      = S + OFF_Q;
    float* k      = S + OFF_K;
    float* v      = S + OFF_V;
    float* ao     = S + OFF_AO;
    float* x2     = S + OFF_X2;
    float* mlp    = S + OFF_MLP;

    const int CH_SMEM = (2*64*132 + 2*4096 + 64) * 4;  // 100864 B
    const int YO_SMEM = (2*64*132 + 64) * 4;           // 67840 B
    const int AT_SMEM = (4*4352 + 192) * 4;            // 70400 B
    cudaFuncSetAttribute(chunk_kernel, cudaFuncAttributeMaxDynamicSharedMemorySize, CH_SMEM);
    cudaFuncSetAttribute(yoff_kernel,  cudaFuncAttributeMaxDynamicSharedMemorySize, YO_SMEM);
    cudaFuncSetAttribute(attn_tc,      cudaFuncAttributeMaxDynamicSharedMemorySize, AT_SMEM);

    // ===== Mamba block =====
    rmsnorm_kernel<<<4096, 256>>>(x, mnw, h);
    gemm_tc<0><<<dim3(35, 32), 256>>>(h, inw, nullptr, zx, 4096, 4384, 1024);
    prep_kernel<<<4096, 256>>>(zx, dtb, Alog, Bnw, Cnw, xdt, acum);
    cumsum_kernel<<<dim3(32, 32, 2), 64>>>(acum);
    chunk_kernel<<<dim3(32, 32, 2), 256, CH_SMEM>>>(zx, xdt, acum, states, y);
    scan_kernel<<<dim3(64, 4), 256>>>(states, acum);
    yoff_kernel<<<dim3(32, 32, 2), 256, YO_SMEM>>>(zx, acum, states, Dp, y);
    gemm_tc<1><<<dim3(8, 32), 256>>>(y, outw, x, x1, 4096, 1024, 2048);

    // ===== Attention block =====
    layernorm_kernel<<<4096, 256>>>(x1, ln1w, ln1b, h);
    gemm_tc<0><<<dim3(8, 32), 256>>>(h, cqw, nullptr, q, 4096, 1024, 1024);
    gemm_tc<0><<<dim3(2, 32), 256>>>(h, ckw, nullptr, k, 4096, 256, 1024);
    gemm_tc<0><<<dim3(2, 32), 256>>>(h, cvw, nullptr, v, 4096, 256, 1024);
    rmsrope_kernel<<<dim3(4096, 16), 32>>>(q, 16, qg);
    rmsrope_kernel<<<dim3(4096, 4), 32>>>(k, 4, nullptr);
    attn_tc<<<dim3(32, 16, 2), 256, AT_SMEM>>>(q, k, v, ao);
    gemm_tc<1><<<dim3(8, 32), 256>>>(ao, cpw, x1, x2, 4096, 1024, 1024);

    // ===== MLP =====
    layernorm_kernel<<<4096, 256>>>(x2, ln2w, ln2b, h);
    gemm_tc<2><<<dim3(24, 32), 256>>>(h, fcw, nullptr, mlp, 4096, 3072, 1024);
    gemm_tc<1><<<dim3(8, 32), 256>>>(mlp, pjw, x2, out, 4096, 1024, 3072);
}

// round 15
// speedup vs baseline: 1.8000x; 1.4971x over previous
#include <cuda_runtime.h>
#include <cuda_bf16.h>
#include <cstdint>
#include <math.h>

#define S_ 2048
#define DPROJ 4384

// ---------- scratch (floats) ----------
#define OFF_H        0ull
#define OFF_ZX       (OFF_H      + 4194304ull)   // 4096*1024
#define OFF_ACUM     (OFF_ZX     + 17956864ull)  // 4096*4384
#define OFF_XDT      (OFF_ACUM   + 131072ull)    // 64*2048
#define OFF_STATES   (OFF_XDT    + 8388608ull)   // 4096*2048
#define OFF_Y        (OFF_STATES + 16777216ull)  // 2*32*32*64*128
#define OFF_X1       (OFF_Y      + 8388608ull)
#define OFF_Q        (OFF_X1     + 4194304ull)
#define OFF_K        (OFF_Q      + 4194304ull)
#define OFF_V        (OFF_K      + 1048576ull)
#define OFF_AO       (OFF_V      + 1048576ull)
#define OFF_X2       (OFF_AO     + 4194304ull)
#define OFF_MLP      (OFF_X2     + 4194304ull)
#define SCRATCH_FLOATS (OFF_MLP + 12582912ull)

__device__ float g_scratch[SCRATCH_FLOATS];

// ---------- helpers ----------
__device__ __forceinline__ float bsum256(float v, float* red) {
    #pragma unroll
    for (int o = 16; o; o >>= 1) v += __shfl_xor_sync(0xffffffffu, v, o);
    if ((threadIdx.x & 31) == 0) red[threadIdx.x >> 5] = v;
    __syncthreads();
    float t = red[0]+red[1]+red[2]+red[3]+red[4]+red[5]+red[6]+red[7];
    __syncthreads();
    return t;
}

__device__ __forceinline__ unsigned f2tf32(float f) {
    unsigned r; asm("cvt.rna.tf32.f32 %0, %1;" : "=r"(r) : "f"(f)); return r;
}

__device__ __forceinline__ void cp16(float* s, const float* g, bool p) {
    unsigned sa = (unsigned)__cvta_generic_to_shared(s);
    int sz = p ? 16 : 0;
    asm volatile("cp.async.cg.shared.global [%0], [%1], 16, %2;" :: "r"(sa), "l"(g), "r"(sz));
}
#define CP_COMMIT() asm volatile("cp.async.commit_group;")
#define CP_WAIT(N)  asm volatile("cp.async.wait_group %0;" :: "n"(N))

__device__ __forceinline__ void mma8(float* c, const unsigned* a, const unsigned* b) {
    asm volatile("mma.sync.aligned.m16n8k8.row.col.f32.tf32.tf32.f32 "
        "{%0,%1,%2,%3},{%4,%5,%6,%7},{%8,%9},{%0,%1,%2,%3};"
        : "+f"(c[0]), "+f"(c[1]), "+f"(c[2]), "+f"(c[3])
        : "r"(a[0]), "r"(a[1]), "r"(a[2]), "r"(a[3]), "r"(b[0]), "r"(b[1]));
}

// ---------- rmsnorm over 1024 ----------
__global__ void __launch_bounds__(256) rmsnorm_kernel(const float* __restrict__ x,
                                                      const float* __restrict__ w,
                                                      float* __restrict__ out) {
    __shared__ float red[8];
    size_t row = blockIdx.x;
    const float* xr = x + (row << 10);
    float v[4]; float ss = 0.f;
    #pragma unroll
    for (int i = 0; i < 4; i++) { v[i] = xr[threadIdx.x + (i << 8)]; ss += v[i]*v[i]; }
    float tot = bsum256(ss, red);
    float sc = rsqrtf(tot * (1.f/1024.f) + 1e-5f);
    float* orow = out + (row << 10);
    #pragma unroll
    for (int i = 0; i < 4; i++) {
        int j = threadIdx.x + (i << 8);
        orow[j] = v[i] * sc * w[j];
    }
}

// ---------- layernorm over 1024 ----------
__global__ void __launch_bounds__(256) layernorm_kernel(const float* __restrict__ x,
                                                        const float* __restrict__ w,
                                                        const float* __restrict__ bb,
                                                        float* __restrict__ out) {
    __shared__ float red[8];
    size_t row = blockIdx.x;
    const float* xr = x + (row << 10);
    float v[4]; float s = 0.f;
    #pragma unroll
    for (int i = 0; i < 4; i++) { v[i] = xr[threadIdx.x + (i << 8)]; s += v[i]; }
    float mean = bsum256(s, red) * (1.f/1024.f);
    float sv = 0.f;
    #pragma unroll
    for (int i = 0; i < 4; i++) { float d = v[i]-mean; sv += d*d; }
    float var = bsum256(sv, red) * (1.f/1024.f);
    float sc = rsqrtf(var + 1e-5f);
    float* orow = out + (row << 10);
    #pragma unroll
    for (int i = 0; i < 4; i++) {
        int j = threadIdx.x + (i << 8);
        orow[j] = (v[i]-mean)*sc*w[j] + bb[j];
    }
}

// ---------- GEMM mainloop core (R9 structure) ----------
#define GEMM_BODY(Aptr, Wptr, NK)                                                \
    float acc[4][4][4];                                                          \
    _Pragma("unroll")                                                            \
    for (int i = 0; i < 4; i++)                                                  \
        _Pragma("unroll")                                                        \
        for (int j = 0; j < 4; j++)                                              \
            _Pragma("unroll")                                                    \
            for (int q = 0; q < 4; q++) acc[i][j][q] = 0.f;                      \
    cp16(&As[0][lr][lk],   Aptr,     true);                                      \
    cp16(&As[0][lr][lk+4], Aptr + 4, true);                                      \
    cp16(&Ws[0][lr][lk],   Wptr,     wok);                                       \
    cp16(&Ws[0][lr][lk+4], Wptr + 4, wok);                                       \
    CP_COMMIT();                                                                 \
    for (int t = 0; t < (NK); t++) {                                             \
        if (t + 1 < (NK)) {                                                      \
            int st = (t + 1) & 1;                                                \
            int ko = (t + 1) << 4;                                               \
            cp16(&As[st][lr][lk],   Aptr + ko,     true);                        \
            cp16(&As[st][lr][lk+4], Aptr + ko + 4, true);                        \
            cp16(&Ws[st][lr][lk],   Wptr + ko,     wok);                         \
            cp16(&Ws[st][lr][lk+4], Wptr + ko + 4, wok);                         \
            CP_COMMIT();                                                         \
            CP_WAIT(1);                                                          \
        } else {                                                                 \
            CP_WAIT(0);                                                          \
        }                                                                        \
        __syncthreads();                                                         \
        int st = t & 1;                                                          \
        _Pragma("unroll")                                                        \
        for (int ks = 0; ks < 2; ks++) {                                         \
            int kb = ks << 3;                                                    \
            int c = kb + (lane & 3);                                             \
            unsigned af[4][4], bf[4][2];                                         \
            _Pragma("unroll")                                                    \
            for (int mt = 0; mt < 4; mt++) {                                     \
                int r = wm + (mt << 4) + (lane >> 2);                            \
                af[mt][0] = f2tf32(As[st][r][c]);                                \
                af[mt][1] = f2tf32(As[st][r+8][c]);                              \
                af[mt][2] = f2tf32(As[st][r][c+4]);                              \
                af[mt][3] = f2tf32(As[st][r+8][c+4]);                            \
            }                                                                    \
            _Pragma("unroll")                                                    \
            for (int nt = 0; nt < 4; nt++) {                                     \
                int n = wn + (nt << 3) + (lane >> 2);                            \
                bf[nt][0] = f2tf32(Ws[st][n][c]);                                \
                bf[nt][1] = f2tf32(Ws[st][n][c+4]);                              \
            }                                                                    \
            _Pragma("unroll")                                                    \
            for (int mt = 0; mt < 4; mt++)                                       \
                _Pragma("unroll")                                                \
                for (int nt = 0; nt < 4; nt++)                                   \
                    mma8(acc[mt][nt], af[mt], bf[nt]);                           \
        }                                                                        \
        __syncthreads();                                                         \
    }

// ---------- tensor-core TF32 GEMM (R9) ----------
template<int EPI>
__global__ void __launch_bounds__(256) gemm_tc(const float* __restrict__ A,
                                               const float* __restrict__ W,
                                               const float* __restrict__ res,
                                               float* __restrict__ out,
                                               int M, int N, int K) {
    __shared__ float As[2][128][20];
    __shared__ float Ws[2][128][20];
    int tid = threadIdx.x;
    int bm = blockIdx.y << 7, bn = blockIdx.x << 7;
    int lane = tid & 31, wid = tid >> 5;
    int wm = (wid & 1) << 6;
    int wn = (wid >> 1) << 5;

    int lr = tid >> 1;
    int lk = (tid & 1) << 3;
    const float* Ag = A + (size_t)(bm + lr) * K + lk;
    int wrow = bn + lr;
    bool wok = wrow < N;
    const float* Wg = W + (size_t)(wok ? wrow : (N-1)) * K + lk;

    GEMM_BODY(Ag, Wg, K >> 4)

    #pragma unroll
    for (int mt = 0; mt < 4; mt++) {
        int r0 = bm + wm + (mt << 4) + (lane >> 2);
        #pragma unroll
        for (int nt = 0; nt < 4; nt++) {
            int c0 = bn + wn + (nt << 3) + ((lane & 3) << 1);
            #pragma unroll
            for (int q = 0; q < 4; q++) {
                int r = r0 + ((q >> 1) << 3);
                int cc = c0 + (q & 1);
                if (cc >= N) continue;
                float v = acc[mt][nt][q];
                if (EPI == 1) v += res[(size_t)r * N + cc];
                if (EPI == 2) v = v / (1.f + expf(-v));
                out[(size_t)r * N + cc] = v;
            }
        }
    }
}

// ---------- fused q/k/v projection GEMM (blocks 0-7 q, 8-9 k, 10-11 v) ----------
__global__ void __launch_bounds__(256) gemm_qkv(const float* __restrict__ A,
                                                const float* __restrict__ Wq,
                                                const float* __restrict__ Wk,
                                                const float* __restrict__ Wv,
                                                float* __restrict__ qo,
                                                float* __restrict__ ko,
                                                float* __restrict__ vo) {
    __shared__ float As[2][128][20];
    __shared__ float Ws[2][128][20];
    const int K = 1024;
    int tid = threadIdx.x;
    int bx = blockIdx.x;
    int bm = blockIdx.y << 7;
    int lane = tid & 31, wid = tid >> 5;
    int wm = (wid & 1) << 6;
    int wn = (wid >> 1) << 5;

    const float* W; float* out; int No; int bn;
    if (bx < 8)       { W = Wq; out = qo; No = 1024; bn = bx << 7; }
    else if (bx < 10) { W = Wk; out = ko; No = 256;  bn = (bx - 8) << 7; }
    else              { W = Wv; out = vo; No = 256;  bn = (bx - 10) << 7; }

    int lr = tid >> 1;
    int lk = (tid & 1) << 3;
    const float* Ag = A + (size_t)(bm + lr) * K + lk;
    bool wok = true;
    const float* Wg = W + (size_t)(bn + lr) * K + lk;

    GEMM_BODY(Ag, Wg, K >> 4)

    #pragma unroll
    for (int mt = 0; mt < 4; mt++) {
        int r0 = bm + wm + (mt << 4) + (lane >> 2);
        #pragma unroll
        for (int nt = 0; nt < 4; nt++) {
            int c0 = bn + wn + (nt << 3) + ((lane & 3) << 1);
            #pragma unroll
            for (int q = 0; q < 4; q++) {
                int r = r0 + ((q >> 1) << 3);
                int cc = c0 + (q & 1);
                out[(size_t)r * No + cc] = acc[mt][nt][q];
            }
        }
    }
}

// ---------- mamba prep ----------
__global__ void __launch_bounds__(256) prep_kernel(float* __restrict__ zx,
                                                   const float* __restrict__ dtb,
                                                   const float* __restrict__ Alog,
                                                   const float* __restrict__ Bnw,
                                                   const float* __restrict__ Cnw,
                                                   float* __restrict__ xdt,
                                                   float* __restrict__ acum) {
    __shared__ float dts[32];
    __shared__ float red[8];
    int token = blockIdx.x;
    int b = token >> 11, s = token & 2047;
    float* Z = zx + (size_t)token * DPROJ;
    int tid = threadIdx.x;
    if (tid < 32) {
        float vraw = Z[4352 + tid] + dtb[tid];
        float dt = (vraw > 20.f) ? vraw : log1pf(expf(vraw));
        dts[tid] = dt;
        acum[(size_t)(b*32 + tid)*2048 + s] = -expf(Alog[tid]) * dt;
    }
    float val = Z[4096 + tid];
    float sq = val * val;
    #pragma unroll
    for (int o = 16; o; o >>= 1) sq += __shfl_xor_sync(0xffffffffu, sq, o);
    if ((tid & 31) == 0) red[tid >> 5] = sq;
    __syncthreads();
    for (int j = tid; j < 2048; j += 256)
        xdt[(size_t)token*2048 + j] = Z[2048 + j] * dts[j >> 6];
    float ss = (tid < 128) ? (red[0]+red[1]+red[2]+red[3]) : (red[4]+red[5]+red[6]+red[7]);
    float scale = rsqrtf(ss * (1.f/128.f) + 1e-5f);
    Z[4096 + tid] = val * scale * ((tid < 128) ? Bnw[tid] : Cnw[tid - 128]);
}

// ---------- per-chunk inclusive cumsum of dA ----------
__global__ void cumsum_kernel(float* __restrict__ acum) {
    __shared__ float a[64];
    int l = threadIdx.x;
    size_t base = ((size_t)(blockIdx.z*32 + blockIdx.y))*2048 + (blockIdx.x << 6);
    a[l] = acum[base + l];
    __syncthreads();
    #pragma unroll
    for (int d = 1; d < 64; d <<= 1) {
        float t = (l >= d) ? a[l-d] : 0.f;
        __syncthreads();
        a[l] += t;
        __syncthreads();
    }
    acum[base + l] = a[l];
}

// ---------- chunk kernel: Y_diag + per-chunk states (R9 scalar) ----------
__global__ void __launch_bounds__(256) chunk_kernel(const float* __restrict__ zx,
                                                    const float* __restrict__ xdt,
                                                    const float* __restrict__ acum,
                                                    float* __restrict__ states,
                                                    float* __restrict__ y) {
    extern __shared__ float sm[];
    float* Bs = sm;               // 64*129
    float* Cs = Bs + 64*129;      // 64*129
    float* Xs = Cs + 64*129;      // 64*64  [s][p]
    float* Sm = Xs + 4096;        // 64*64  [l][s]
    float* Ac = Sm + 4096;        // 64
    int b = blockIdx.z, h = blockIdx.y, c = blockIdx.x;
    int tid = threadIdx.x;
    int row0 = (b << 11) + (c << 6);

    for (int i = tid; i < 8192; i += 256) {
        int l = i >> 7, n = i & 127;
        const float* Z = zx + (size_t)(row0 + l) * DPROJ;
        Bs[l*129 + n] = Z[4096 + n];
        Cs[l*129 + n] = Z[4224 + n];
    }
    for (int i = tid; i < 4096; i += 256) {
        int s = i >> 6, p = i & 63;
        Xs[i] = xdt[(size_t)(row0 + s)*2048 + h*64 + p];
    }
    if (tid < 64) Ac[tid] = acum[(size_t)((b<<5) + h)*2048 + (c<<6) + tid];
    __syncthreads();

    int tx = tid & 15, ty = tid >> 4;
    {
        float acc[4][4];
        #pragma unroll
        for (int i = 0; i < 4; i++)
            #pragma unroll
            for (int j = 0; j < 4; j++) acc[i][j] = 0.f;
        for (int n = 0; n < 128; n++) {
            float rc[4], rb[4];
            #pragma unroll
            for (int i = 0; i < 4; i++) rc[i] = Cs[(ty*4+i)*129 + n];
            #pragma unroll
            for (int j = 0; j < 4; j++) rb[j] = Bs[(tx*4+j)*129 + n];
            #pragma unroll
            for (int i = 0; i < 4; i++)
                #pragma unroll
                for (int j = 0; j < 4; j++) acc[i][j] += rc[i]*rb[j];
        }
        #pragma unroll
        for (int i = 0; i < 4; i++)
            #pragma unroll
            for (int j = 0; j < 4; j++) {
                int l = ty*4+i, s = tx*4+j;
                Sm[l*64 + s] = (l >= s) ? acc[i][j]*expf(Ac[l]-Ac[s]) : 0.f;
            }
    }
    __syncthreads();
    {
        float acc[4][4];
        #pragma unroll
        for (int i = 0; i < 4; i++)
            #pragma unroll
            for (int j = 0; j < 4; j++) acc[i][j] = 0.f;
        for (int s = 0; s < 64; s++) {
            float rs[4], rx[4];
            #pragma unroll
            for (int i = 0; i < 4; i++) rs[i] = Sm[(ty*4+i)*64 + s];
            #pragma unroll
            for (int j = 0; j < 4; j++) rx[j] = Xs[s*64 + tx*4+j];
            #pragma unroll
            for (int i = 0; i < 4; i++)
                #pragma unroll
                for (int j = 0; j < 4; j++) acc[i][j] += rs[i]*rx[j];
        }
        #pragma unroll
        for (int i = 0; i < 4; i++)
            #pragma unroll
            for (int j = 0; j < 4; j++)
                y[(size_t)(row0 + ty*4+i)*2048 + h*64 + tx*4+j] = acc[i][j];
    }
    float alast = Ac[63];
    for (int i = tid; i < 8192; i += 256) {
        int l = i >> 7, n = i & 127;
        Bs[l*129 + n] *= expf(alast - Ac[l]);
    }
    __syncthreads();
    {
        float acc[4][8];
        #pragma unroll
        for (int i = 0; i < 4; i++)
            #pragma unroll
            for (int j = 0; j < 8; j++) acc[i][j] = 0.f;
        for (int l = 0; l < 64; l++) {
            float rx[4], rb[8];
            #pragma unroll
            for (int i = 0; i < 4; i++) rx[i] = Xs[l*64 + ty*4+i];
            #pragma unroll
            for (int j = 0; j < 8; j++) rb[j] = Bs[l*129 + tx*8+j];
            #pragma unroll
            for (int i = 0; i < 4; i++)
                #pragma unroll
                for (int j = 0; j < 8; j++) acc[i][j] += rx[i]*rb[j];
        }
        size_t base = ((size_t)((b*32 + c)*32 + h)) * 8192;
        #pragma unroll
        for (int i = 0; i < 4; i++)
            #pragma unroll
            for (int j = 0; j < 8; j++)
                states[base + (ty*4+i)*128 + tx*8+j] = acc[i][j];
    }
}

// ---------- inter-chunk scan (widened: 256 blocks, bit-identical math) ----------
__global__ void __launch_bounds__(256) scan_kernel(float* __restrict__ states,
                                                   const float* __restrict__ acum) {
    int bh = blockIdx.x;
    int b = bh >> 5, h = bh & 31;
    int sl = blockIdx.y;   // 0..3
    int tid = threadIdx.x;
    float st[8];
    #pragma unroll
    for (int r = 0; r < 8; r++) st[r] = 0.f;
    for (int z = 0; z < 32; z++) {
        float ed = expf(acum[(size_t)bh*2048 + z*64 + 63]);
        size_t base = ((size_t)((b*32 + z)*32 + h)) * 8192;
        #pragma unroll
        for (int r = 0; r < 8; r++) {
            size_t idx = base + tid + ((sl*8 + r) << 8);
            float old = states[idx];
            states[idx] = st[r];
            st[r] = ed*st[r] + old;
        }
    }
}

// ---------- Y_off + D-skip + silu gate (R9 scalar) ----------
__global__ void __launch_bounds__(256) yoff_kernel(const float* __restrict__ zx,
                                                   const float* __restrict__ acum,
                                                   const float* __restrict__ states,
                                                   const float* __restrict__ Dp,
                                                   float* __restrict__ y) {
    extern __shared__ float sm[];
    float* Cs = sm;               // 64*129  [l][n]
    float* NS = Cs + 64*129;      // 64*129  [p][n]
    float* Ac = NS + 64*129;      // 64
    int b = blockIdx.z, h = blockIdx.y, c = blockIdx.x;
    int tid = threadIdx.x;
    int row0 = (b << 11) + (c << 6);
    for (int i = tid; i < 8192; i += 256) {
        int l = i >> 7, n = i & 127;
        Cs[l*129 + n] = zx[(size_t)(row0 + l)*DPROJ + 4224 + n];
    }
    size_t sbase = ((size_t)((b*32 + c)*32 + h)) * 8192;
    for (int i = tid; i < 8192; i += 256)
        NS[(i >> 7)*129 + (i & 127)] = states[sbase + i];
    if (tid < 64) Ac[tid] = acum[(size_t)((b<<5) + h)*2048 + (c<<6) + tid];
    __syncthreads();

    int tx = tid & 15, ty = tid >> 4;
    float acc[4][4];
    #pragma unroll
    for (int i = 0; i < 4; i++)
        #pragma unroll
        for (int j = 0; j < 4; j++) acc[i][j] = 0.f;
    for (int n = 0; n < 128; n++) {
        float rc[4], rn[4];
        #pragma unroll
        for (int i = 0; i < 4; i++) rc[i] = Cs[(ty*4+i)*129 + n];
        #pragma unroll
        for (int j = 0; j < 4; j++) rn[j] = NS[(tx*4+j)*129 + n];
        #pragma unroll
        for (int i = 0; i < 4; i++)
            #pragma unroll
            for (int j = 0; j < 4; j++) acc[i][j] += rc[i]*rn[j];
    }
    float dph = Dp[h];
    #pragma unroll
    for (int i = 0; i < 4; i++) {
        int l = ty*4+i;
        float eA = expf(Ac[l]);
        size_t token = row0 + l;
        const float* Z = zx + token * DPROJ;
        #pragma unroll
        for (int j = 0; j < 4; j++) {
            int p = tx*4+j;
            float xs = Z[2048 + h*64 + p];
            float zg = Z[h*64 + p];
            size_t yi = token*2048 + h*64 + p;
            float v = y[yi] + eA*acc[i][j] + xs*dph;
            v *= zg / (1.f + expf(-zg));
            y[yi] = v;
        }
    }
}

// ---------- per-head rmsnorm + rope + optional gain ----------
__global__ void rmsrope_kernel(float* __restrict__ X, int nheads, const float* __restrict__ gain) {
    int token = blockIdx.x;
    int h = blockIdx.y;
    int s = token & (S_ - 1);
    float* p = X + (size_t)token*nheads*64 + (size_t)h*64;
    int lane = threadIdx.x;
    float v0 = p[lane], v1 = p[lane + 32];
    float ss = v0*v0 + v1*v1;
    #pragma unroll
    for (int o = 16; o; o >>= 1) ss += __shfl_xor_sync(0xffffffffu, ss, o);
    float sc = rsqrtf(ss * (1.f/64.f) + 1.1920929e-7f);
    v0 *= sc; v1 *= sc;
    float oth = __shfl_xor_sync(0xffffffffu, v0, 8);
    if (lane < 16) {
        int i = lane & 7;
        float inv = powf(10000.f, -(float)i * 0.125f);
        float f = (float)s * inv;
        float cf = cosf(f), sf = sinf(f);
        v0 = (lane < 8) ? (v0*cf + oth*sf) : (v0*cf - oth*sf);
    }
    if (gain) { float g = gain[h]; v0 *= g; v1 *= g; }
    p[lane] = v0; p[lane + 32] = v1;
}

// ---------- tensor-core causal flash attention, 64-row blocks, GQA 4:1 ----------
__global__ void __launch_bounds__(256) attn_tc(const float* __restrict__ Q,
                                               const float* __restrict__ K,
                                               const float* __restrict__ V,
                                               float* __restrict__ O) {
    extern __shared__ float sm[];
    float* Qs = sm;            // 64*68
    float* Ks = Qs + 4352;     // 64*68 [key][d]
    float* Vt = Ks + 4352;     // 64*68 [d][key]
    float* Ss = Vt + 4352;     // 64*68 [row][key] scores/P
    float* rowm   = Ss + 4352; // 64
    float* rowl   = rowm + 64; // 64
    float* ralpha = rowl + 64; // 64
    int b = blockIdx.z, h = blockIdx.y;
    int qt = 31 - blockIdx.x;           // big tiles first
    int tid = threadIdx.x;
    int lane = tid & 31, wid = tid >> 5;
    int mt = (wid & 3) << 4;            // 0,16,32,48
    int nh = (wid >> 2) << 5;           // 0 or 32
    int kvh = h >> 2;
    int r0 = mt + (lane >> 2);

    for (int i = tid; i < 4096; i += 256) {
        int r = i >> 6, c = i & 63;
        Qs[r*68 + c] = Q[(size_t)((b<<11) + (qt<<6) + r)*1024 + h*64 + c];
    }
    if (tid < 64) { rowm[tid] = -1e30f; rowl[tid] = 0.f; }

    float o[4][4];
    #pragma unroll
    for (int nt = 0; nt < 4; nt++)
        #pragma unroll
        for (int q = 0; q < 4; q++) o[nt][q] = 0.f;

    for (int kt = 0; kt <= qt; kt++) {
        __syncthreads();
        for (int i = tid; i < 4096; i += 256) {
            int rr = i >> 6, cc = i & 63;
            size_t idx = (size_t)((b<<11) + (kt<<6) + rr)*256 + kvh*64 + cc;
            Ks[rr*68 + cc] = K[idx];
            Vt[cc*68 + rr] = V[idx];
        }
        __syncthreads();

        float sf[4][4];
        #pragma unroll
        for (int nt = 0; nt < 4; nt++)
            #pragma unroll
            for (int q = 0; q < 4; q++) sf[nt][q] = 0.f;
        #pragma unroll
        for (int k8 = 0; k8 < 8; k8++) {
            int c = (k8 << 3) + (lane & 3);
            unsigned af[4];
            af[0] = f2tf32(Qs[r0*68 + c]);
            af[1] = f2tf32(Qs[(r0+8)*68 + c]);
            af[2] = f2tf32(Qs[r0*68 + c + 4]);
            af[3] = f2tf32(Qs[(r0+8)*68 + c + 4]);
            #pragma unroll
            for (int nt = 0; nt < 4; nt++) {
                int n = nh + (nt << 3) + (lane >> 2);
                unsigned bf[2] = { f2tf32(Ks[n*68 + c]), f2tf32(Ks[n*68 + c + 4]) };
                mma8(sf[nt], af, bf);
            }
        }
        #pragma unroll
        for (int nt = 0; nt < 4; nt++) {
            int c0 = nh + (nt << 3) + ((lane & 3) << 1);
            #pragma unroll
            for (int q = 0; q < 4; q++) {
                int rr = r0 + ((q >> 1) << 3);
                int cc = c0 + (q & 1);
                float s = sf[nt][q] * 0.125f;
                if (kt == qt && cc > rr) s = -1e30f;
                Ss[rr*68 + cc] = s;
            }
        }
        __syncthreads();

        {
            int sr = tid >> 2, scol = (tid & 3) << 4;
            float mloc = -1e30f;
            #pragma unroll
            for (int j = 0; j < 16; j++) mloc = fmaxf(mloc, Ss[sr*68 + scol + j]);
            mloc = fmaxf(mloc, __shfl_xor_sync(0xffffffffu, mloc, 1));
            mloc = fmaxf(mloc, __shfl_xor_sync(0xffffffffu, mloc, 2));
            float mold = rowm[sr];
            float newm = fmaxf(mold, mloc);
            float suml = 0.f;
            #pragma unroll
            for (int j = 0; j < 16; j++) {
                float p = expf(Ss[sr*68 + scol + j] - newm);
                Ss[sr*68 + scol + j] = p;
                suml += p;
            }
            suml += __shfl_xor_sync(0xffffffffu, suml, 1);
            suml += __shfl_xor_sync(0xffffffffu, suml, 2);
            if ((tid & 3) == 0) {
                float a = expf(mold - newm);
                ralpha[sr] = a;
                rowm[sr] = newm;
                rowl[sr] = a * rowl[sr] + suml;
            }
        }
        __syncthreads();

        float a0 = ralpha[r0], a1 = ralpha[r0 + 8];
        #pragma unroll
        for (int nt = 0; nt < 4; nt++) {
            o[nt][0] *= a0; o[nt][1] *= a0;
            o[nt][2] *= a1; o[nt][3] *= a1;
        }
        #pragma unroll
        for (int k8 = 0; k8 < 8; k8++) {
            int c = (k8 << 3) + (lane & 3);
            unsigned af[4];
            af[0] = f2tf32(Ss[r0*68 + c]);
            af[1] = f2tf32(Ss[(r0+8)*68 + c]);
            af[2] = f2tf32(Ss[r0*68 + c + 4]);
            af[3] = f2tf32(Ss[(r0+8)*68 + c + 4]);
            #pragma unroll
            for (int nt = 0; nt < 4; nt++) {
                int n = nh + (nt << 3) + (lane >> 2);
                unsigned bf[2] = { f2tf32(Vt[n*68 + c]), f2tf32(Vt[n*68 + c + 4]) };
                mma8(o[nt], af, bf);
            }
        }
    }

    float l0 = 1.f / rowl[r0], l1 = 1.f / rowl[r0 + 8];
    #pragma unroll
    for (int nt = 0; nt < 4; nt++) {
        int c0 = nh + (nt << 3) + ((lane & 3) << 1);
        #pragma unroll
        for (int q = 0; q < 4; q++) {
            int rr = r0 + ((q >> 1) << 3);
            int cc = c0 + (q & 1);
            O[(size_t)((b<<11) + (qt<<6) + rr)*1024 + h*64 + cc] =
                o[nt][q] * ((q < 2) ? l0 : l1);
        }
    }
}

// ---------- launch ----------
extern "C" void kernel_launch(void* const* d_in, const int* in_sizes, int n_in,
                              void* d_out, int out_size) {
    const float* x     = (const float*)d_in[0];
    const float* mnw   = (const float*)d_in[1];
    const float* inw   = (const float*)d_in[2];
    const float* outw  = (const float*)d_in[3];
    const float* Dp    = (const float*)d_in[4];
    const float* dtb   = (const float*)d_in[5];
    const float* Alog  = (const float*)d_in[6];
    const float* Bnw   = (const float*)d_in[7];
    const float* Cnw   = (const float*)d_in[8];
    const float* ln1w  = (const float*)d_in[9];
    const float* ln1b  = (const float*)d_in[10];
    const float* cqw   = (const float*)d_in[11];
    const float* ckw   = (const float*)d_in[12];
    const float* cvw   = (const float*)d_in[13];
    const float* cpw   = (const float*)d_in[14];
    const float* qg    = (const float*)d_in[15];
    const float* ln2w  = (const float*)d_in[16];
    const float* ln2b  = (const float*)d_in[17];
    const float* fcw   = (const float*)d_in[18];
    const float* pjw   = (const float*)d_in[19];
    float* out = (float*)d_out;

    float* S = nullptr;
    cudaGetSymbolAddress((void**)&S, g_scratch);
    float* h      = S + OFF_H;
    float* zx     = S + OFF_ZX;
    float* acum   = S + OFF_ACUM;
    float* xdt    = S + OFF_XDT;
    float* states = S + OFF_STATES;
    float* y      = S + OFF_Y;
    float* x1     = S + OFF_X1;
    float* q      = S + OFF_Q;
    float* k      = S + OFF_K;
    float* v      = S + OFF_V;
    float* ao     = S + OFF_AO;
    float* x2     = S + OFF_X2;
    float* mlp    = S + OFF_MLP;

    const int CH_SMEM = (2*64*129 + 2*4096 + 64) * 4;
    const int YO_SMEM = (2*64*129 + 64) * 4;
    const int AT_SMEM = (4*4352 + 192) * 4;
    cudaFuncSetAttribute(chunk_kernel, cudaFuncAttributeMaxDynamicSharedMemorySize, CH_SMEM);
    cudaFuncSetAttribute(yoff_kernel,  cudaFuncAttributeMaxDynamicSharedMemorySize, YO_SMEM);
    cudaFuncSetAttribute(attn_tc,      cudaFuncAttributeMaxDynamicSharedMemorySize, AT_SMEM);

    // ===== Mamba block =====
    rmsnorm_kernel<<<4096, 256>>>(x, mnw, h);
    gemm_tc<0><<<dim3(35, 32), 256>>>(h, inw, nullptr, zx, 4096, 4384, 1024);
    prep_kernel<<<4096, 256>>>(zx, dtb, Alog, Bnw, Cnw, xdt, acum);
    cumsum_kernel<<<dim3(32, 32, 2), 64>>>(acum);
    chunk_kernel<<<dim3(32, 32, 2), 256, CH_SMEM>>>(zx, xdt, acum, states, y);
    scan_kernel<<<dim3(64, 4), 256>>>(states, acum);
    yoff_kernel<<<dim3(32, 32, 2), 256, YO_SMEM>>>(zx, acum, states, Dp, y);
    gemm_tc<1><<<dim3(8, 32), 256>>>(y, outw, x, x1, 4096, 1024, 2048);

    // ===== Attention block =====
    layernorm_kernel<<<4096, 256>>>(x1, ln1w, ln1b, h);
    gemm_qkv<<<dim3(12, 32), 256>>>(h, cqw, ckw, cvw, q, k, v);
    rmsrope_kernel<<<dim3(4096, 16), 32>>>(q, 16, qg);
    rmsrope_kernel<<<dim3(4096, 4), 32>>>(k, 4, nullptr);
    attn_tc<<<dim3(32, 16, 2), 256, AT_SMEM>>>(q, k, v, ao);
    gemm_tc<1><<<dim3(8, 32), 256>>>(ao, cpw, x1, x2, 4096, 1024, 1024);

    // ===== MLP =====
    layernorm_kernel<<<4096, 256>>>(x2, ln2w, ln2b, h);
    gemm_tc<2><<<dim3(24, 32), 256>>>(h, fcw, nullptr, mlp, 4096, 3072, 1024);
    gemm_tc<1><<<dim3(8, 32), 256>>>(mlp, pjw, x2, out, 4096, 1024, 3072);
}